// round 5
// baseline (speedup 1.0000x reference)
#include <cuda_runtime.h>
#include <cuda_bf16.h>
#include <cstdint>

// ---------------------------------------------------------------------------
// TargetTokenEncoder: hist/stats -> MLP(14->256, exact GELU) -> GEMM(256x256)
// Stage C via warp-level HMMA (mma.sync m16n8k16 bf16, fp32 accum),
// bf16x3 split precision: Ah*Bh + Ah*Bl + Al*Bh (rel err ~5e-6).
// R5: double-buffered B chunks (16 kcols, stride 48) via cp.async so fills
//     overlap MMA; A XOR-swizzled stride 512; stats overlaid in B-buf1;
//     b2 from gmem in epilogue. smem = 114688 -> still 2 CTAs/SM.
// ---------------------------------------------------------------------------

static constexpr int S      = 128;
static constexpr int TD     = 256;
static constexpr int TILE_M = 64;

static constexpr int A_STRIDE = 512;              // swizzled, no pad
static constexpr int N_KC    = 16;                // 16 k-chunks of 16 cols
static constexpr int B_STRIDE = 48;               // 16 bf16 (32B) + 16B pad
static constexpr int B_HALF  = 256 * B_STRIDE;    // 12288 (hi or lo)
static constexpr int B_BUF   = 2 * B_HALF;        // 24576 per buffer

static constexpr int OFF_A_HI  = 0;               // 64 x 512 = 32768
static constexpr int OFF_A_LO  = 32768;
static constexpr int OFF_B0    = 65536;           // buffer 0 (hi, then lo)
static constexpr int OFF_B1    = 90112;           // buffer 1 (hi, then lo)
static constexpr int OFF_STATS = 90112;           // OVERLAY: dead before 1st B1 fill
static constexpr int SMEM_BYTES = 114688;         // 14 x 8KB granules

static constexpr int D_A_LO = OFF_A_LO - OFF_A_HI;   // 32768
static constexpr int D_B_LO = B_HALF;                // 12288 within a buffer

// persistent scratch: w2 split-bf16, exact smem B-chunk byte image per kc
__device__ __align__(16) __nv_bfloat16 g_b_hi[N_KC * 256 * (B_STRIDE / 2)];
__device__ __align__(16) __nv_bfloat16 g_b_lo[N_KC * 256 * (B_STRIDE / 2)];

__device__ __forceinline__ uint32_t smem_u32(const void* p) {
    uint32_t a;
    asm("{ .reg .u64 t; cvta.to.shared.u64 t, %1; cvt.u32.u64 %0, t; }" : "=r"(a) : "l"(p));
    return a;
}

__device__ __forceinline__ void cp16(uint32_t saddr, const void* gptr) {
    asm volatile("cp.async.cg.shared.global [%0], [%1], 16;"
                 :: "r"(saddr), "l"(gptr) : "memory");
}

__device__ __forceinline__ void cp_commit() {
    asm volatile("cp.async.commit_group;" ::: "memory");
}

__device__ __forceinline__ void cp_wait0() {
    asm volatile("cp.async.wait_group 0;" ::: "memory");
}

__device__ __forceinline__ void cp_wait1() {
    asm volatile("cp.async.wait_group 1;" ::: "memory");
}

__device__ __forceinline__ void ldm4(uint32_t* r, uint32_t addr) {
    asm volatile("ldmatrix.sync.aligned.m8n8.x4.shared.b16 {%0,%1,%2,%3}, [%4];"
                 : "=r"(r[0]), "=r"(r[1]), "=r"(r[2]), "=r"(r[3]) : "r"(addr));
}

__device__ __forceinline__ void mma_bf16(float* c, const uint32_t* a,
                                         uint32_t b0, uint32_t b1) {
    asm volatile("mma.sync.aligned.m16n8k16.row.col.f32.bf16.bf16.f32 "
                 "{%0,%1,%2,%3}, {%4,%5,%6,%7}, {%8,%9}, {%0,%1,%2,%3};"
                 : "+f"(c[0]), "+f"(c[1]), "+f"(c[2]), "+f"(c[3])
                 : "r"(a[0]), "r"(a[1]), "r"(a[2]), "r"(a[3]), "r"(b0), "r"(b1));
}

// ---------------- prep kernel: split w2 into chunked smem-image layout
// chunk kc, n-row nl, slot j (24 slots of 2B; j<16 = data k = kc*16+j)
__global__ __launch_bounds__(256)
void prep_kernel(const float* __restrict__ w2) {
    int idx = blockIdx.x * 256 + threadIdx.x;
    const int total = N_KC * 256 * (B_STRIDE / 2);      // 98304
    if (idx >= total) return;
    int kc  = idx / (256 * 24);
    int rem = idx % (256 * 24);
    int nl  = rem / 24;
    int j   = rem % 24;
    float v = (j < 16) ? __ldg(w2 + (size_t)(kc * 16 + j) * TD + nl) : 0.0f;
    __nv_bfloat16 hi = __float2bfloat16(v);
    float lo = v - __bfloat162float(hi);
    g_b_hi[idx] = hi;
    g_b_lo[idx] = __float2bfloat16(lo);
}

// copy one pre-split B chunk (hi+lo) into an smem buffer via cp.async
__device__ __forceinline__ void fill_b_copy(uint32_t sbuf, int kc,
                                            int tid0, int nthreads) {
    const char* shi = reinterpret_cast<const char*>(g_b_hi) + kc * B_HALF;
    const char* slo = reinterpret_cast<const char*>(g_b_lo) + kc * B_HALF;
    for (int i = tid0; i < B_HALF / 16; i += nthreads) {
        cp16(sbuf + i * 16, shi + i * 16);
        cp16(sbuf + D_B_LO + i * 16, slo + i * 16);
    }
    cp_commit();
}

__global__ __launch_bounds__(256, 2)
void tte_kernel(const int* __restrict__ y, const float* __restrict__ w1,
                const float* __restrict__ b1,
                const float* __restrict__ b2, float* __restrict__ out)
{
    extern __shared__ char smem[];
    const uint32_t sb = smem_u32(smem);
    const int tid = threadIdx.x;
    const int wid = tid >> 5;
    const int lid = tid & 31;

    float* stats = reinterpret_cast<float*>(smem + OFF_STATS);

    // ---------------- Phase 1: threads 0-63 histogram+stats for 64 rows;
    //                  threads 64-255 prefetch B chunk 0 into buffer 0
    if (tid < TILE_M) {
        const int4* p = reinterpret_cast<const int4*>(
            y + ((size_t)blockIdx.x * TILE_M + tid) * S);
        uint32_t a0 = 0, a1 = 0, a2 = 0;   // 4x8-bit packed counters
        #pragma unroll
        for (int i = 0; i < S / 4; i++) {
            int4 v = __ldg(p + i);
            { int x = v.x; uint32_t b = 1u << ((x & 3) << 3);
              if (x < 4) a0 += b; else if (x < 8) a1 += b; else a2 += b; }
            { int x = v.y; uint32_t b = 1u << ((x & 3) << 3);
              if (x < 4) a0 += b; else if (x < 8) a1 += b; else a2 += b; }
            { int x = v.z; uint32_t b = 1u << ((x & 3) << 3);
              if (x < 4) a0 += b; else if (x < 8) a1 += b; else a2 += b; }
            { int x = v.w; uint32_t b = 1u << ((x & 3) << 3);
              if (x < 4) a0 += b; else if (x < 8) a1 += b; else a2 += b; }
        }
        int cnt[10];
        float pr[10];
        #pragma unroll
        for (int c = 0; c < 10; c++) {
            uint32_t a = (c < 4) ? a0 : ((c < 8) ? a1 : a2);
            cnt[c] = (int)((a >> ((c & 3) * 8)) & 0xFF);
            pr[c]  = (float)cnt[c] * (1.0f / 128.0f);   // exact in fp32
        }
        float ent = 0.0f, pm = 0.0f, nnz = 0.0f;
        #pragma unroll
        for (int c = 0; c < 10; c++) {
            ent -= pr[c] * logf(pr[c] + 1e-6f);         // p==0 -> exactly 0
            pm   = fmaxf(pm, pr[c]);
            nnz += (cnt[c] > 0) ? 1.0f : 0.0f;
        }
        float* sr = stats + tid * 16;
        #pragma unroll
        for (int c = 0; c < 10; c++) sr[c] = pr[c];
        sr[10] = nnz; sr[11] = ent; sr[12] = 128.0f; sr[13] = pm;
        sr[14] = 0.0f; sr[15] = 0.0f;
    } else {
        fill_b_copy(sb + OFF_B0, 0, tid - 64, 192);
        cp_wait0();                      // producers confirm chunk 0 landed
    }
    __syncthreads();

    // ---------------- Phase 2: stage-B MLP. thread t owns h column n=t.
    //                  A stored split bf16, XOR-granule swizzle, stride 512.
    {
        float wv[14];
        #pragma unroll
        for (int k = 0; k < 14; k++) wv[k] = __ldg(w1 + k * TD + tid);
        const float bb = __ldg(b1 + tid);
        const uint32_t gc = (uint32_t)(tid >> 3);        // 16B granule of col
        const uint32_t gi = (uint32_t)((tid & 7) << 1);  // byte within granule
        for (int r = 0; r < TILE_M; r++) {
            const float4* sp = reinterpret_cast<const float4*>(stats + r * 16);
            float4 s0 = sp[0], s1 = sp[1], s2 = sp[2], s3 = sp[3];
            float x = bb;
            x = fmaf(s0.x, wv[0], x);  x = fmaf(s0.y, wv[1], x);
            x = fmaf(s0.z, wv[2], x);  x = fmaf(s0.w, wv[3], x);
            x = fmaf(s1.x, wv[4], x);  x = fmaf(s1.y, wv[5], x);
            x = fmaf(s1.z, wv[6], x);  x = fmaf(s1.w, wv[7], x);
            x = fmaf(s2.x, wv[8], x);  x = fmaf(s2.y, wv[9], x);
            x = fmaf(s2.z, wv[10], x); x = fmaf(s2.w, wv[11], x);
            x = fmaf(s3.x, wv[12], x); x = fmaf(s3.y, wv[13], x);
            float g = 0.5f * x * (1.0f + erff(x * 0.707106781186547524f));
            __nv_bfloat16 hi = __float2bfloat16(g);
            float rem = g - __bfloat162float(hi);
            __nv_bfloat16 lo = __float2bfloat16(rem);
            uint32_t off = (uint32_t)(r * A_STRIDE)
                         + (((gc ^ (uint32_t)(r & 7)) << 4) | gi);
            *reinterpret_cast<__nv_bfloat16*>(smem + OFF_A_HI + off) = hi;
            *reinterpret_cast<__nv_bfloat16*>(smem + OFF_A_LO + off) = lo;
        }
    }
    __syncthreads();   // stats dead from here; B1 region reusable

    // ---------------- Phase 3: GEMM h[64,256] @ w2[256,256], bf16x3 HMMA
    // 8 warps = 2 (M, 32 rows) x 4 (N, 64 cols). Chunk = 16 k-cols.
    const int wm = wid >> 2;           // 0..1
    const int wn = wid & 3;            // 0..3
    const int mo = wm * 32;
    const int j8 = lid >> 3;           // 8x8 matrix selector
    const int lr = lid & 7;

    // A: per-thread row base + row-swizzle key; k-granule = kc*2 + (j8>>1)
    uint32_t arow[2], arx[2];
    #pragma unroll
    for (int i = 0; i < 2; i++) {
        const int rr = mo + i * 16 + ((j8 & 1) << 3) + lr;
        arow[i] = sb + OFF_A_HI + (uint32_t)(rr * A_STRIDE);
        arx[i]  = (uint32_t)(rr & 7);
    }
    const uint32_t agj = (uint32_t)(j8 >> 1);

    // B: per-thread offset within a buffer (n-row stride 48, k granule j8&1)
    uint32_t brel[4];
    #pragma unroll
    for (int p = 0; p < 4; p++)
        brel[p] = (uint32_t)((wn * 64 + p * 16 + ((j8 >> 1) << 3) + lr) * B_STRIDE)
                + (uint32_t)((j8 & 1) << 4);

    float acc[2][8][4];
    #pragma unroll
    for (int i = 0; i < 2; i++)
        #pragma unroll
        for (int j = 0; j < 8; j++)
            #pragma unroll
            for (int q = 0; q < 4; q++) acc[i][j][q] = 0.0f;

    #pragma unroll 1
    for (int kc = 0; kc < N_KC; kc++) {
        if (kc + 1 < N_KC) {
            fill_b_copy(sb + ((kc + 1) & 1 ? OFF_B1 : OFF_B0), kc + 1, tid, 256);
            cp_wait1();                 // chunk kc arrived; kc+1 in flight
        } else {
            cp_wait0();
        }
        __syncthreads();                // data visible to all warps

        const uint32_t bbuf = sb + ((kc & 1) ? OFF_B1 : OFF_B0);
        uint32_t aH[2][4], aL[2][4];
        #pragma unroll
        for (int i = 0; i < 2; i++) {
            const uint32_t ga = ((uint32_t)(kc * 2) + agj) ^ arx[i];
            ldm4(aH[i], arow[i] + (ga << 4));
            ldm4(aL[i], arow[i] + (ga << 4) + D_A_LO);
        }
        #pragma unroll
        for (int p = 0; p < 4; p++) {
            uint32_t bH[4], bL[4];
            ldm4(bH, bbuf + brel[p]);
            ldm4(bL, bbuf + brel[p] + D_B_LO);
            #pragma unroll
            for (int i = 0; i < 2; i++) {
                #pragma unroll
                for (int jj = 0; jj < 2; jj++) {
                    const int j = p * 2 + jj, h = jj * 2;
                    mma_bf16(acc[i][j], aH[i], bH[h], bH[h + 1]); // Ah*Bh
                    mma_bf16(acc[i][j], aH[i], bL[h], bL[h + 1]); // Ah*Bl
                    mma_bf16(acc[i][j], aL[i], bH[h], bH[h + 1]); // Al*Bh
                }
            }
        }
        __syncthreads();                // reads done before next overwrite
    }

    // ---------------- Epilogue (b2 straight from gmem: L1/L2 resident)
    {
        const int g  = lid >> 2;           // c-frag row within tile
        const int tg = lid & 3;            // c-frag col pair
        const size_t rbase = (size_t)blockIdx.x * TILE_M;
        #pragma unroll
        for (int i = 0; i < 2; i++) {
            #pragma unroll
            for (int j = 0; j < 8; j++) {
                const int col = wn * 64 + j * 8 + tg * 2;
                const float2 bb = __ldg(reinterpret_cast<const float2*>(b2 + col));
                const size_t r0 = rbase + mo + i * 16 + g;
                float2 v0 = make_float2(acc[i][j][0] + bb.x, acc[i][j][1] + bb.y);
                float2 v1 = make_float2(acc[i][j][2] + bb.x, acc[i][j][3] + bb.y);
                *reinterpret_cast<float2*>(out + r0 * TD + col) = v0;
                *reinterpret_cast<float2*>(out + (r0 + 8) * TD + col) = v1;
            }
        }
    }
}

extern "C" void kernel_launch(void* const* d_in, const int* in_sizes, int n_in,
                              void* d_out, int out_size) {
    const int*   y  = (const int*)d_in[0];
    const float* w1 = (const float*)d_in[1];
    const float* b1 = (const float*)d_in[2];
    const float* w2 = (const float*)d_in[3];
    const float* b2 = (const float*)d_in[4];
    float* out = (float*)d_out;
    const int Btot = in_sizes[0] / S;          // 65536 rows
    const int grid = Btot / TILE_M;            // 1024 CTAs

    // split w2 -> bf16 hi/lo scratch (smem image layout), then fused kernel
    prep_kernel<<<(N_KC * 256 * (B_STRIDE / 2) + 255) / 256, 256>>>(w2);

    cudaFuncSetAttribute(tte_kernel, cudaFuncAttributeMaxDynamicSharedMemorySize,
                         SMEM_BYTES);
    tte_kernel<<<grid, 256, SMEM_BYTES>>>(y, w1, b1, b2, out);
}